// round 4
// baseline (speedup 1.0000x reference)
#include <cuda_runtime.h>

// ---------------- problem constants (fixed shapes) ----------------
#define BB   4
#define CC   64
#define HH   288
#define WW   432
#define PW   72            // W / TEM
#define TEM_ 6
#define VV   (HH*WW)       // 124416
#define RN   ((HH-1)*PW)   // 20664  vertical edges per phase
#define CN   (HH*(PW-1))   // 20448  horizontal edges per phase
#define XN   (HH*PW)       // 20736  cross edges per phase pair
#define PB   (RN+CN)       // 41112  weight-layout per-phase block
#define EE   (6*RN+6*CN+5*XN) // 350352 total edges
#define NOUT (VV-1)        // 124415 output entries per batch
#define SENT 0xFFFFFFFFFFFFFFFFULL
#define NROUNDS 18

// ---------------- scratch (device globals; no allocation) ----------------
__device__ unsigned long long g_keys[BB*EE];     // (w_bits<<32)|e at weight-layout position e
__device__ unsigned long long g_minkey[BB*VV];   // per-component min key
__device__ int g_comp[BB*VV];
__device__ int g_parent[BB*VV];
__device__ int g_mask[BB*EE];

// endpoints of edge e in INDEX layout: [rows x6 | cols x6 | cross x5]
__device__ __forceinline__ void edge_uv(int e, int& u, int& v) {
    if (e < 6*RN) {
        int i = e / RN; int j = e - i*RN;
        int r = j / PW;  int c = j - r*PW;
        u = r*WW + i*PW + c; v = u + WW;
    } else if (e < 6*RN + 6*CN) {
        int t = e - 6*RN;
        int i = t / CN; int j = t - i*CN;
        int r = j / (PW-1); int c = j - r*(PW-1);
        u = r*WW + i*PW + c; v = u + 1;
    } else {
        int t = e - 6*RN - 6*CN;
        int i = t / XN; int j = t - i*XN;
        int r = j / PW; int c = j - r*PW;
        u = r*WW + i*PW + c; v = u + PW;
    }
}

// ---------------- init ----------------
__global__ void init_kernel() {
    int idx = blockIdx.x * blockDim.x + threadIdx.x;
    if (idx < BB*VV) {
        g_comp[idx]   = idx % VV;
        g_minkey[idx] = SENT;
    }
    if (idx < BB*EE) g_mask[idx] = 0;
}

// ---------------- weights: thread-per-pixel (down / right / cross-right) ----
// WEIGHT layout: phase i block at i*PB: [vertical RN | horizontal CN]; cross at 6*PB.
__global__ void weight_kernel(const float* __restrict__ fm) {
    int idx = blockIdx.x * blockDim.x + threadIdx.x;
    if (idx >= BB*VV) return;
    int b   = idx / VV;
    int pix = idx - b*VV;
    int r   = pix / WW;
    int col = pix - r*WW;
    int ph  = col / PW;
    int c   = col - ph*PW;

    bool hasV = (r  < HH-1);
    bool hasH = (c  < PW-1);
    bool hasX = (ph < TEM_-1);

    const float* base = fm + (size_t)b * CC * VV + pix;
    float sv = 0.f, sh = 0.f, sx = 0.f;
    #pragma unroll 8
    for (int ch = 0; ch < CC; ch++) {
        const float* p = base + (size_t)ch * VV;
        float x0 = __ldg(p);
        if (hasV) { float d = x0 - __ldg(p + WW); sv += d*d; }
        if (hasH) { float d = x0 - __ldg(p + 1);  sh += d*d; }
        if (hasX) { float d = x0 - __ldg(p + PW); sx += d*d; }
    }
    unsigned long long* kb = g_keys + (size_t)b * EE;
    if (hasV) {
        int e = ph*PB + r*PW + c;
        kb[e] = ((unsigned long long)__float_as_uint(sv) << 32) | (unsigned)e;
    }
    if (hasH) {
        int e = ph*PB + RN + r*(PW-1) + c;
        kb[e] = ((unsigned long long)__float_as_uint(sh) << 32) | (unsigned)e;
    }
    if (hasX) {
        int e = 6*PB + ph*XN + r*PW + c;
        kb[e] = ((unsigned long long)__float_as_uint(sx) << 32) | (unsigned)e;
    }
}

// ---------------- Boruvka round ----------------
__global__ void edge_kernel() {
    int e = blockIdx.x * blockDim.x + threadIdx.x;
    if (e >= EE) return;
    int b = blockIdx.y;
    int u, v; edge_uv(e, u, v);
    int cu = g_comp[b*VV + u];
    int cv = g_comp[b*VV + v];
    if (cu == cv) return;
    unsigned long long k = g_keys[(size_t)b*EE + e];
    atomicMin(&g_minkey[b*VV + cu], k);
    atomicMin(&g_minkey[b*VV + cv], k);
}

__global__ void select_kernel() {
    int c = blockIdx.x * blockDim.x + threadIdx.x;
    if (c >= VV) return;
    int b = blockIdx.y;
    unsigned long long mk = g_minkey[b*VV + c];
    int par = c;
    if (mk != SENT) {
        g_minkey[b*VV + c] = SENT;                 // reset for next round
        int e = (int)(unsigned)(mk & 0xFFFFFFFFu);
        g_mask[b*EE + e] = 1;                      // idempotent
        int u, v; edge_uv(e, u, v);
        int a = g_comp[b*VV + u];
        int d = g_comp[b*VV + v];
        par = (a == c) ? d : a;
    }
    g_parent[b*VV + c] = par;
}

// chase to root; mutual (2-cycle) pair resolves to min of the pair (matches reference)
__global__ void chase_kernel() {
    int vtx = blockIdx.x * blockDim.x + threadIdx.x;
    if (vtx >= VV) return;
    int b = blockIdx.y;
    const int* par = g_parent + b*VV;
    int c = g_comp[b*VV + vtx];
    while (true) {
        int p = par[c];
        if (p == c) break;
        int gp = par[p];
        if (gp == c) { c = (c < p) ? c : p; break; }
        c = p;
    }
    g_comp[b*VV + vtx] = c;
}

// ---------------- output (FLOAT32): prefill pad, then streaming compaction ----
__global__ void prefill_kernel(float* out, int total) {
    int i = blockIdx.x * blockDim.x + threadIdx.x;
    if (i < total) out[i] = (float)EE;
}

// One block per batch; 1024 threads x 4 edges each, ascending-order stable compaction.
__global__ void compact_kernel(float* __restrict__ out, int stride) {
    int b    = blockIdx.x;
    int tid  = threadIdx.x;
    int lane = tid & 31;
    int w    = tid >> 5;

    __shared__ int wsum[32];
    __shared__ int s_base;
    __shared__ int s_total;
    if (tid == 0) s_base = 0;
    __syncthreads();

    const int* mb = g_mask + b*EE;
    float* ob = out + (size_t)b*stride;

    for (int chunk = 0; chunk < EE; chunk += 4096) {
        int e0 = chunk + tid*4;
        int m0 = (e0 + 0 < EE) ? mb[e0 + 0] : 0;
        int m1 = (e0 + 1 < EE) ? mb[e0 + 1] : 0;
        int m2 = (e0 + 2 < EE) ? mb[e0 + 2] : 0;
        int m3 = (e0 + 3 < EE) ? mb[e0 + 3] : 0;
        int cnt = m0 + m1 + m2 + m3;

        int inc = cnt;
        #pragma unroll
        for (int off = 1; off < 32; off <<= 1) {
            int y = __shfl_up_sync(0xffffffffu, inc, off);
            if (lane >= off) inc += y;
        }
        if (lane == 31) wsum[w] = inc;
        __syncthreads();
        if (w == 0) {
            int v = wsum[lane];
            int iv = v;
            #pragma unroll
            for (int off = 1; off < 32; off <<= 1) {
                int y = __shfl_up_sync(0xffffffffu, iv, off);
                if (lane >= off) iv += y;
            }
            wsum[lane] = iv - v;          // exclusive warp offsets
            if (lane == 31) s_total = iv; // block total this chunk
        }
        __syncthreads();

        int base = s_base;
        int pos = base + wsum[w] + (inc - cnt);
        if (m0) { if (pos < stride) ob[pos] = (float)(e0 + 0); pos++; }
        if (m1) { if (pos < stride) ob[pos] = (float)(e0 + 1); pos++; }
        if (m2) { if (pos < stride) ob[pos] = (float)(e0 + 2); pos++; }
        if (m3) { if (pos < stride) ob[pos] = (float)(e0 + 3); pos++; }

        __syncthreads();
        if (tid == 0) s_base = base + s_total;
        __syncthreads();
    }
}

// ---------------- launch ----------------
extern "C" void kernel_launch(void* const* d_in, const int* in_sizes, int n_in,
                              void* d_out, int out_size) {
    const float* fm = (const float*)d_in[0];
    float* out = (float*)d_out;
    (void)in_sizes; (void)n_in;

    int stride = (out_size % BB == 0) ? (out_size / BB) : NOUT;

    const int T = 256;
    int initBlocks = (BB*EE + T - 1) / T;   // covers both BB*EE and BB*VV ranges
    init_kernel<<<initBlocks, T>>>();

    int wBlocks = (BB*VV + T - 1) / T;
    weight_kernel<<<wBlocks, T>>>(fm);

    dim3 egrid((EE + T - 1) / T, BB);
    dim3 vgrid((VV + T - 1) / T, BB);
    for (int r = 0; r < NROUNDS; r++) {
        edge_kernel  <<<egrid, T>>>();
        select_kernel<<<vgrid, T>>>();
        chase_kernel <<<vgrid, T>>>();
    }

    prefill_kernel<<<(out_size + T - 1) / T, T>>>(out, out_size);
    compact_kernel<<<BB, 1024>>>(out, stride);
}